// round 2
// baseline (speedup 1.0000x reference)
#include <cuda_runtime.h>
#include <stdint.h>

#define DW    32     // D_WORLDS
#define K2D   64     // 2*D_WORLDS
#define NW    512    // N_WORLDS
#define BATCH 2048

// Packed dual-fp32 FMA (sm_100+ PTX-only)
#define FMA2(dst, a, b, c) \
    asm("fma.rn.f32x2 %0, %1, %2, %3;" : "=l"(dst) : "l"(a), "l"(b), "l"(c))

__global__ __launch_bounds__(256, 2)
void binop_fused_kernel(const float* __restrict__ states,   // [8*2048, 32, 512]
                        const float* __restrict__ W,        // [128, 32, 64]
                        const float* __restrict__ b,        // [128, 32]
                        const int*   __restrict__ indices,  // [2048]
                        const int*   __restrict__ symbols,  // [2048]
                        const int*   __restrict__ args,     // [2048, 2]
                        float*       __restrict__ out)      // [2048, 32, 512]
{
    // Duplicated W tile: ws2[d*64 + k] = {W[sym][d][k], W[sym][d][k]}
    __shared__ __align__(16) float2 ws2[DW * K2D];   // 16 KB
    __shared__ float bsh[DW];
    __shared__ float sqp[2][128][4];                 // partial sq sums per d-half

    const int n  = blockIdx.x;
    const int t  = threadIdx.x;
    const int dh = t >> 7;        // which half of d (0: d 0..15, 1: d 16..31)
    const int cg = t & 127;       // column group: owns world cols 4cg..4cg+3
    const int d0 = dh * 16;

    const int idx = indices[n];
    const int sym = symbols[n];
    const int a0  = args[2 * n];
    const int a1  = args[2 * n + 1];

    // Load + duplicate W[sym] into smem
    const float* Wp = W + (size_t)sym * (DW * K2D);
    for (int i = t; i < DW * K2D; i += 256) {
        float v = Wp[i];
        ws2[i] = make_float2(v, v);
    }
    if (t < DW) bsh[t] = b[sym * DW + t];
    __syncthreads();

    // x rows: k<32 from left state (d=k), k>=32 from right state (d=k-32).
    // float4 view: row k at +k*128, this thread's 4 cols at +cg.
    const float4* xl = (const float4*)(states + (size_t)(a0 * BATCH + idx) * (DW * NW)) + cg;
    const float4* xr = (const float4*)(states + (size_t)(a1 * BATCH + idx) * (DW * NW)) + cg;

    // acc[dd][p]: packed pair p of this thread's 4 columns, for d = d0+dd
    uint64_t acc[16][2];
    #pragma unroll
    for (int dd = 0; dd < 16; dd++) {
        float bv = bsh[d0 + dd];
        uint64_t pb;
        asm("mov.b64 %0, {%1,%2};" : "=l"(pb) : "f"(bv), "f"(bv));
        acc[dd][0] = pb;
        acc[dd][1] = pb;
    }

    // Double-buffered chunks of 4 k-rows (16 chunks total: 8 left, 8 right)
    float4 xb[2][4];
    #pragma unroll
    for (int j = 0; j < 4; j++) xb[0][j] = xl[(size_t)j * 128];

    #pragma unroll 1
    for (int c = 0; c < 16; c++) {
        const int cur = c & 1, nxt = cur ^ 1;
        if (c < 15) {
            const int cn = c + 1;
            const float4* p = (cn < 8) ? (xl + (size_t)cn * 512)
                                       : (xr + (size_t)(cn - 8) * 512);
            #pragma unroll
            for (int j = 0; j < 4; j++) xb[nxt][j] = p[(size_t)j * 128];
        }

        const int kbase = c * 4;
        #pragma unroll
        for (int kp = 0; kp < 2; kp++) {
            const uint64_t* xa = (const uint64_t*)&xb[cur][2 * kp];      // row k
            const uint64_t* xc = (const uint64_t*)&xb[cur][2 * kp + 1];  // row k+1
            const uint64_t x0lo = xa[0], x0hi = xa[1];
            const uint64_t x1lo = xc[0], x1hi = xc[1];
            const int k = kbase + 2 * kp;
            #pragma unroll
            for (int dd = 0; dd < 16; dd++) {
                // One broadcast LDS.128: {dup w[d][k], dup w[d][k+1]} -> 4 FMA2
                ulonglong2 wv = *(const ulonglong2*)&ws2[(d0 + dd) * K2D + k];
                FMA2(acc[dd][0], wv.x, x0lo, acc[dd][0]);
                FMA2(acc[dd][1], wv.x, x0hi, acc[dd][1]);
                FMA2(acc[dd][0], wv.y, x1lo, acc[dd][0]);
                FMA2(acc[dd][1], wv.y, x1hi, acc[dd][1]);
            }
        }
    }

    // Partial squared sums over this thread's 16 d's, per column
    float sq[4] = {0.f, 0.f, 0.f, 0.f};
    #pragma unroll
    for (int dd = 0; dd < 16; dd++) {
        float2 v0 = *(float2*)&acc[dd][0];
        float2 v1 = *(float2*)&acc[dd][1];
        sq[0] = fmaf(v0.x, v0.x, sq[0]);
        sq[1] = fmaf(v0.y, v0.y, sq[1]);
        sq[2] = fmaf(v1.x, v1.x, sq[2]);
        sq[3] = fmaf(v1.y, v1.y, sq[3]);
    }
    #pragma unroll
    for (int j = 0; j < 4; j++) sqp[dh][cg][j] = sq[j];
    __syncthreads();

    float s[4];
    #pragma unroll
    for (int j = 0; j < 4; j++) {
        float tot = sqp[0][cg][j] + sqp[1][cg][j];
        s[j] = rsqrtf(fmaxf(tot, 1e-12f));
    }

    // Scatter row = indices[n] (arange -> bijective, plain stores)
    float4* op = (float4*)(out + (size_t)idx * (DW * NW)) + cg;
    #pragma unroll
    for (int dd = 0; dd < 16; dd++) {
        float2 v0 = *(float2*)&acc[dd][0];
        float2 v1 = *(float2*)&acc[dd][1];
        float4 r = make_float4(v0.x * s[0], v0.y * s[1], v1.x * s[2], v1.y * s[3]);
        op[(size_t)(d0 + dd) * 128] = r;
    }
}

extern "C" void kernel_launch(void* const* d_in, const int* in_sizes, int n_in,
                              void* d_out, int out_size) {
    const float* states  = (const float*)d_in[0];
    const float* W       = (const float*)d_in[1];
    const float* b       = (const float*)d_in[2];
    const int*   indices = (const int*)d_in[3];
    const int*   symbols = (const int*)d_in[4];
    const int*   args    = (const int*)d_in[5];
    float*       out     = (float*)d_out;

    binop_fused_kernel<<<BATCH, 256>>>(states, W, b, indices, symbols, args, out);
}

// round 3
// speedup vs baseline: 1.2970x; 1.2970x over previous
#include <cuda_runtime.h>
#include <stdint.h>

#define DW    32     // D_WORLDS
#define K2D   64     // 2*D_WORLDS
#define NW    512    // N_WORLDS
#define BATCH 2048

// Packed dual-fp32 FMA (sm_100+ PTX-only)
#define FMA2(dst, a, b, c) \
    asm("fma.rn.f32x2 %0, %1, %2, %3;" : "=l"(dst) : "l"(a), "l"(b), "l"(c))

__device__ __forceinline__ void load4(float4 x[4], const float4* __restrict__ p) {
    #pragma unroll
    for (int j = 0; j < 4; j++) x[j] = p[(size_t)j * 128];   // row stride = 512 floats
}

// Process 4 k-rows held in x[0..3] against 16 d's. wrow = ws2 + d0*K2D + kbase.
__device__ __forceinline__ void proc4(uint64_t acc[16][2], const float4 x[4],
                                      const float2* __restrict__ wrow) {
    #pragma unroll
    for (int kp = 0; kp < 2; kp++) {
        const uint64_t x0lo = ((const uint64_t*)&x[2 * kp])[0];
        const uint64_t x0hi = ((const uint64_t*)&x[2 * kp])[1];
        const uint64_t x1lo = ((const uint64_t*)&x[2 * kp + 1])[0];
        const uint64_t x1hi = ((const uint64_t*)&x[2 * kp + 1])[1];
        #pragma unroll
        for (int dd = 0; dd < 16; dd++) {
            // One broadcast LDS.128: {dup w[d][k], dup w[d][k+1]} -> 4 FMA2
            ulonglong2 wv = *(const ulonglong2*)(wrow + (size_t)dd * K2D + 2 * kp);
            FMA2(acc[dd][0], wv.x, x0lo, acc[dd][0]);
            FMA2(acc[dd][1], wv.x, x0hi, acc[dd][1]);
            FMA2(acc[dd][0], wv.y, x1lo, acc[dd][0]);
            FMA2(acc[dd][1], wv.y, x1hi, acc[dd][1]);
        }
    }
}

__global__ __launch_bounds__(256, 2)
void binop_fused_kernel(const float* __restrict__ states,   // [8*2048, 32, 512]
                        const float* __restrict__ W,        // [128, 32, 64]
                        const float* __restrict__ b,        // [128, 32]
                        const int*   __restrict__ indices,  // [2048]
                        const int*   __restrict__ symbols,  // [2048]
                        const int*   __restrict__ args,     // [2048, 2]
                        float*       __restrict__ out)      // [2048, 32, 512]
{
    // Duplicated W tile: ws2[d*64 + k] = {W[sym][d][k], W[sym][d][k]}
    __shared__ __align__(16) float2 ws2[DW * K2D];   // 16 KB
    __shared__ float bsh[DW];
    __shared__ float sqp[2][128][4];                 // partial sq sums per d-half

    const int n  = blockIdx.x;
    const int t  = threadIdx.x;
    const int dh = t >> 7;        // d-half: 0 -> d 0..15, 1 -> d 16..31
    const int cg = t & 127;       // owns world cols 4cg..4cg+3
    const int d0 = dh * 16;

    const int idx = indices[n];
    const int sym = symbols[n];
    const int a0  = args[2 * n];
    const int a1  = args[2 * n + 1];

    // Load + duplicate W[sym] into smem
    const float* Wp = W + (size_t)sym * (DW * K2D);
    for (int i = t; i < DW * K2D; i += 256) {
        float v = Wp[i];
        ws2[i] = make_float2(v, v);
    }
    if (t < DW) bsh[t] = b[sym * DW + t];
    __syncthreads();

    // x rows: chunks 0..7 from left state, 8..15 from right (4 k-rows each)
    const float4* xl = (const float4*)(states + (size_t)(a0 * BATCH + idx) * (DW * NW)) + cg;
    const float4* xr = (const float4*)(states + (size_t)(a1 * BATCH + idx) * (DW * NW)) + cg;

    uint64_t acc[16][2];
    #pragma unroll
    for (int dd = 0; dd < 16; dd++) {
        float bv = bsh[d0 + dd];
        uint64_t pb;
        asm("mov.b64 %0, {%1,%2};" : "=l"(pb) : "f"(bv), "f"(bv));
        acc[dd][0] = pb;
        acc[dd][1] = pb;
    }

    const float2* wbase = ws2 + d0 * K2D;

    // Double-buffered, spill-free: named buffers, parity static (c += 2)
    float4 xa[4], xb[4];
    load4(xa, xl);   // chunk 0

    #pragma unroll 1
    for (int c = 0; c < 16; c += 2) {
        // prefetch chunk c+1
        const int c1 = c + 1;
        const float4* p1 = (c1 < 8) ? (xl + (size_t)c1 * 512) : (xr + (size_t)(c1 - 8) * 512);
        load4(xb, p1);

        proc4(acc, xa, wbase + c * 4);

        // prefetch chunk c+2 (clamped at tail; harmless reload)
        const int c2 = (c + 2 < 16) ? (c + 2) : 15;
        const float4* p2 = (c2 < 8) ? (xl + (size_t)c2 * 512) : (xr + (size_t)(c2 - 8) * 512);
        load4(xa, p2);

        proc4(acc, xb, wbase + c1 * 4);
    }

    // Partial squared sums over this thread's 16 d's, per column
    float sq[4] = {0.f, 0.f, 0.f, 0.f};
    #pragma unroll
    for (int dd = 0; dd < 16; dd++) {
        float2 v0 = *(float2*)&acc[dd][0];
        float2 v1 = *(float2*)&acc[dd][1];
        sq[0] = fmaf(v0.x, v0.x, sq[0]);
        sq[1] = fmaf(v0.y, v0.y, sq[1]);
        sq[2] = fmaf(v1.x, v1.x, sq[2]);
        sq[3] = fmaf(v1.y, v1.y, sq[3]);
    }
    #pragma unroll
    for (int j = 0; j < 4; j++) sqp[dh][cg][j] = sq[j];
    __syncthreads();

    float s[4];
    #pragma unroll
    for (int j = 0; j < 4; j++) {
        float tot = sqp[0][cg][j] + sqp[1][cg][j];
        s[j] = rsqrtf(fmaxf(tot, 1e-12f));
    }

    // Scatter row = indices[n] (arange -> bijective, plain stores)
    float4* op = (float4*)(out + (size_t)idx * (DW * NW)) + cg;
    #pragma unroll
    for (int dd = 0; dd < 16; dd++) {
        float2 v0 = *(float2*)&acc[dd][0];
        float2 v1 = *(float2*)&acc[dd][1];
        float4 r = make_float4(v0.x * s[0], v0.y * s[1], v1.x * s[2], v1.y * s[3]);
        op[(size_t)(d0 + dd) * 128] = r;
    }
}

extern "C" void kernel_launch(void* const* d_in, const int* in_sizes, int n_in,
                              void* d_out, int out_size) {
    const float* states  = (const float*)d_in[0];
    const float* W       = (const float*)d_in[1];
    const float* b       = (const float*)d_in[2];
    const int*   indices = (const int*)d_in[3];
    const int*   symbols = (const int*)d_in[4];
    const int*   args    = (const int*)d_in[5];
    float*       out     = (float*)d_out;

    binop_fused_kernel<<<BATCH, 256>>>(states, W, b, indices, symbols, args, out);
}